// round 9
// baseline (speedup 1.0000x reference)
#include <cuda_runtime.h>
#include <cuda_fp16.h>
#include <mma.h>
#include <cstdint>

using namespace nvcuda;

#define N_MESH 40962
#define N_GRID 262144
#define N_EDGE 786432

// ------------------------------ device scratch ------------------------------
__device__ float  g_agg[(size_t)N_GRID * 128];
__device__ __half g_W1e[384 * 256];   // [K][N], fp16-RN pre-rounded
__device__ __half g_W2e[256 * 128];
__device__ __half g_W1n[256 * 256];
__device__ __half g_W2n[256 * 128];
__device__ __half g_meshH[(size_t)N_MESH * 256];   // mesh @ W1e[128:256]
__device__ __half g_gridH[(size_t)N_GRID * 256];   // grid @ W1e[256:384]

#define MT    64
#define NTHR  256

// ---------------- node kernel smem layout (unchanged from R8) ----------------
#define SM_CONST_B1 0
#define SM_CONST_B2 1024
#define SM_CONST_G  1536
#define SM_CONST_BT 2048
#define SM_A(b)    (2560 + (b) * 9216)
#define SM_B1(s)   (20992 + (s) * 33792)
#define SM_B2(s)   (20992 + (s) * 17408)
#define SM_HH      55808
#define SM_SCR(w)  (89600 + (w) * 1280)
#define SM_Y       20992
#define SMEM_BYTES 99840

#define LDA   72
#define LDB1  264
#define LDB2  136
#define LDHH  264
#define LDY   132
#define LDSCR 20

// ---------------- edge kernel v3 smem layout ----------------
#define SE_A(b)   (2560 + (b) * 5120)      // half, 64 x 40 (K32 chunks), double
#define SE_B1(s)  (12800 + (s) * 16896)    // half, 32 x 264 (K32), double
#define SE_B2(s)  (2560 + (s) * 17408)     // half, 64 x 136 (K64), double (dead A/B1)
#define SE_HH     46592                     // half, 64 x 264 (MGH sum, then SiLU'd H)
#define SE_SCR(w) (80384 + (w) * 1280)
#define SE_Y      46592                     // float, 64 x 132 (HH dead after GEMM2)
#define SE_SMEM   90624
#define LDA_E     40

// ---------------- prepH kernel smem layout ----------------
#define PH_A(b)   ((b) * 9216)             // half, 64 x 72 (K64), double
#define PH_B(s)   (18432 + (s) * 33792)    // half, 64 x 264 (K64), double
#define PH_SCR(w) (86016 + (w) * 1280)
#define PH_SMEM   96256

// ------------------------------ helpers -------------------------------------
__device__ __forceinline__ uint32_t smem_u32(const void* p) {
    uint32_t a;
    asm("{ .reg .u64 t; cvta.to.shared.u64 t, %1; cvt.u32.u64 %0, t; }" : "=r"(a) : "l"(p));
    return a;
}
__device__ __forceinline__ void cpa16(uint32_t s, const void* g) {
    asm volatile("cp.async.cg.shared.global [%0], [%1], 16;" :: "r"(s), "l"(g) : "memory");
}
__device__ __forceinline__ void cp_commit() {
    asm volatile("cp.async.commit_group;" ::: "memory");
}
__device__ __forceinline__ void cp_wait0() {
    asm volatile("cp.async.wait_group 0;" ::: "memory");
}
__device__ __forceinline__ void red_add_v4(float* p, float4 v) {
    asm volatile("red.global.add.v4.f32 [%0], {%1, %2, %3, %4};"
                 :: "l"(p), "f"(v.x), "f"(v.y), "f"(v.z), "f"(v.w) : "memory");
}
__device__ __forceinline__ uint4 pack8h(float4 a, float4 b) {
    __half2 h0 = __floats2half2_rn(a.x, a.y);
    __half2 h1 = __floats2half2_rn(a.z, a.w);
    __half2 h2 = __floats2half2_rn(b.x, b.y);
    __half2 h3 = __floats2half2_rn(b.z, b.w);
    uint4 u;
    u.x = *reinterpret_cast<uint32_t*>(&h0);
    u.y = *reinterpret_cast<uint32_t*>(&h1);
    u.z = *reinterpret_cast<uint32_t*>(&h2);
    u.w = *reinterpret_cast<uint32_t*>(&h3);
    return u;
}
__device__ __forceinline__ uint32_t hadd2u(uint32_t a, uint32_t b) {
    __half2 r = __hadd2(*reinterpret_cast<__half2*>(&a), *reinterpret_cast<__half2*>(&b));
    return *reinterpret_cast<uint32_t*>(&r);
}
__device__ __forceinline__ uint4 hadd2u4(uint4 a, uint4 b) {
    uint4 r;
    r.x = hadd2u(a.x, b.x); r.y = hadd2u(a.y, b.y);
    r.z = hadd2u(a.z, b.z); r.w = hadd2u(a.w, b.w);
    return r;
}
__device__ __forceinline__ float4 silu4(float4 x) {
    float4 s;
    s.x = x.x / (1.f + __expf(-x.x)); s.y = x.y / (1.f + __expf(-x.y));
    s.z = x.z / (1.f + __expf(-x.z)); s.w = x.w / (1.f + __expf(-x.w));
    return s;
}

typedef wmma::fragment<wmma::matrix_a, 16, 16, 16, __half, wmma::row_major> AFrag;
typedef wmma::fragment<wmma::matrix_b, 16, 16, 16, __half, wmma::row_major> BFrag;
typedef wmma::fragment<wmma::accumulator, 16, 16, 16, float> CFrag;

// ------------------------------ prep kernels --------------------------------
__global__ void zero_agg_kernel() {
    size_t i = (size_t)blockIdx.x * blockDim.x + threadIdx.x;
    reinterpret_cast<float4*>(g_agg)[i] = make_float4(0.f, 0.f, 0.f, 0.f);
}
__global__ void prep_kernel(const float* __restrict__ eW1, const float* __restrict__ eW2,
                            const float* __restrict__ nW1, const float* __restrict__ nW2) {
    int i = blockIdx.x * blockDim.x + threadIdx.x;
    if (i < 98304)       g_W1e[i]          = __float2half_rn(eW1[i]);
    else if (i < 131072) g_W2e[i - 98304]  = __float2half_rn(eW2[i - 98304]);
    else if (i < 196608) g_W1n[i - 131072] = __float2half_rn(nW1[i - 131072]);
    else if (i < 229376) g_W2n[i - 196608] = __float2half_rn(nW2[i - 196608]);
}

// dense H precompute: out[R,256] fp16 = in[R,128] @ W[128,256]
// wsel: 0 -> W = g_W1e rows 128..255 (mesh part); 1 -> rows 256..383 (grid part)
__global__ void __launch_bounds__(NTHR, 2)
prepH_kernel(const float* __restrict__ in, int R, int wsel, __half* __restrict__ out)
{
    extern __shared__ char smc[];
    const uint32_t sb = smem_u32(smc);
    const int tid  = threadIdx.x;
    const int warp = tid >> 5, lane = tid & 31;
    const int wm = warp >> 2, wn = warp & 3;
    const int n0 = blockIdx.x * MT;
    const __half* W = g_W1e + (wsel ? 256 * 256 : 128 * 256);

    const int r  = tid >> 2;
    const int cb = (tid & 3) * 16;
    const int rclamp = min(n0 + r, R - 1);
    const float* rowp = in + (size_t)rclamp * 128;

    float4 v0, v1, v2, v3;
    auto ldgA = [&](int c) {
        const float4* gp = (const float4*)(rowp + c * 64 + cb);
        v0 = __ldg(gp); v1 = __ldg(gp + 1); v2 = __ldg(gp + 2); v3 = __ldg(gp + 3);
    };
    auto stsA = [&](int c) {
        char* d = smc + PH_A(c & 1) + (r * LDA + cb) * 2;
        *(uint4*)(d)      = pack8h(v0, v1);
        *(uint4*)(d + 16) = pack8h(v2, v3);
    };
    auto stageB = [&](int c) {
        uint32_t bb = sb + PH_B(c & 1);
        const __half* gw = W + c * 64 * 256;
        #pragma unroll
        for (int i = 0; i < 8; ++i) {
            int id = tid + NTHR * i; int rw = id >> 5, c16 = id & 31;
            cpa16(bb + (uint32_t)(rw * LDB1 + c16 * 8) * 2, gw + rw * 256 + c16 * 8);
        }
    };

    CFrag acc[2][4];
    #pragma unroll
    for (int i = 0; i < 2; i++)
        #pragma unroll
        for (int j = 0; j < 4; j++) wmma::fill_fragment(acc[i][j], 0.f);

    ldgA(0); stageB(0); cp_commit(); stsA(0); ldgA(1);

    #pragma unroll 1
    for (int c = 0; c < 2; ++c) {
        cp_wait0();
        __syncthreads();
        if (c == 0) { stageB(1); cp_commit(); }
        const __half* ab = (const __half*)(smc + PH_A(c & 1));
        const __half* bb = (const __half*)(smc + PH_B(c & 1));
        #pragma unroll
        for (int kk = 0; kk < 64; kk += 16) {
            AFrag a0, a1;
            wmma::load_matrix_sync(a0, ab + (wm * 32)      * LDA + kk, LDA);
            wmma::load_matrix_sync(a1, ab + (wm * 32 + 16) * LDA + kk, LDA);
            #pragma unroll
            for (int j = 0; j < 4; j++) {
                BFrag b;
                wmma::load_matrix_sync(b, bb + kk * LDB1 + wn * 64 + j * 16, LDB1);
                wmma::mma_sync(acc[0][j], a0, b, acc[0][j]);
                wmma::mma_sync(acc[1][j], a1, b, acc[1][j]);
            }
        }
        if (c == 0) stsA(1);
    }

    // acc -> fp16 out (no bias, no activation)
    {
        float* scr = (float*)(smc + PH_SCR(warp));
        const int rr = lane >> 1, ch = (lane & 1) * 8;
        #pragma unroll
        for (int i = 0; i < 2; i++)
            #pragma unroll
            for (int j = 0; j < 4; j++) {
                wmma::store_matrix_sync(scr, acc[i][j], LDSCR, wmma::mem_row_major);
                __syncwarp();
                const float* p = scr + rr * LDSCR + ch;
                float4 x0 = *(const float4*)(p);
                float4 x1 = *(const float4*)(p + 4);
                int grow = n0 + wm * 32 + i * 16 + rr;
                int cbase = wn * 64 + j * 16 + ch;
                if (grow < R)
                    *(uint4*)(out + (size_t)grow * 256 + cbase) = pack8h(x0, x1);
                __syncwarp();
            }
    }
}

// ------------------------------ edge kernel v3 -------------------------------
// GEMM1a: efeat[64,128] @ W1a[128,256] (4 K32 chunks)
// + gather meshH[src] + gridH[dst] (H-space), +b1, SiLU -> HH
// GEMM2: HH[64,256] @ W2e[256,128] (4 K64 chunks) -> LN -> scatter
__global__ void __launch_bounds__(NTHR, 2)
edge_kernel(const float* __restrict__ efeat,
            const int* __restrict__ src, const int* __restrict__ dst,
            const float* __restrict__ b1, const float* __restrict__ b2,
            const float* __restrict__ gam, const float* __restrict__ bet)
{
    extern __shared__ char smc[];
    const uint32_t sb = smem_u32(smc);
    const int tid  = threadIdx.x;
    const int warp = tid >> 5, lane = tid & 31;
    const int wm = warp >> 2, wn = warp & 3;
    const int e0 = blockIdx.x * MT;

    if (tid < 64) ((float4*)(smc + SM_CONST_B1))[tid] = ((const float4*)b1)[tid];
    else if (tid < 96)  ((float4*)(smc + SM_CONST_B2))[tid - 64] = ((const float4*)b2)[tid - 64];
    else if (tid < 128) ((float4*)(smc + SM_CONST_G ))[tid - 96] = ((const float4*)gam)[tid - 96];
    else if (tid < 160) ((float4*)(smc + SM_CONST_BT))[tid - 128] = ((const float4*)bet)[tid - 128];

    const int r  = tid >> 2;
    const int q  = tid & 3;
    const int sidx = __ldg(&src[e0 + r]);
    const int didx = __ldg(&dst[e0 + r]);
    const float* rowE = efeat + (size_t)(e0 + r) * 128;

    // cp.async meshH[src] rows into HH region early (fully hidden by GEMM1a)
    {
        uint32_t hdst = sb + SE_HH + (uint32_t)(r * LDHH + q * 64) * 2;
        const __half* msrc = g_meshH + (size_t)sidx * 256 + q * 64;
        #pragma unroll
        for (int i = 0; i < 8; ++i)
            cpa16(hdst + i * 16, msrc + i * 8);
        cp_commit();
    }

    float4 v0, v1;
    auto ldgA = [&](int c) {   // chunk c: efeat cols c*32 + q*8 .. +7
        const float4* gp = (const float4*)(rowE + c * 32 + q * 8);
        v0 = __ldg(gp); v1 = __ldg(gp + 1);
    };
    auto stsA = [&](int c) {
        *(uint4*)(smc + SE_A(c & 1) + (r * LDA_E + q * 8) * 2) = pack8h(v0, v1);
    };
    auto stageB1 = [&](int c) {
        uint32_t bb = sb + SE_B1(c & 1);
        const __half* gw = g_W1e + c * 32 * 256;   // W1a = rows 0..127
        #pragma unroll
        for (int i = 0; i < 4; ++i) {
            int id = tid + NTHR * i; int rw = id >> 5, c16 = id & 31;
            cpa16(bb + (uint32_t)(rw * LDB1 + c16 * 8) * 2, gw + rw * 256 + c16 * 8);
        }
    };
    auto stageB2 = [&](int c) {
        uint32_t bb = sb + SE_B2(c & 1);
        const __half* gw = g_W2e + c * 64 * 128;
        #pragma unroll
        for (int i = 0; i < 4; ++i) {
            int id = tid + NTHR * i; int rw = id >> 4, c16 = id & 15;
            cpa16(bb + (uint32_t)(rw * LDB2 + c16 * 8) * 2, gw + rw * 128 + c16 * 8);
        }
    };

    // ---------------- GEMM1a: [64,128]x[128,256], 4 K32 chunks ----------------
    CFrag acc[2][4];
    #pragma unroll
    for (int i = 0; i < 2; i++)
        #pragma unroll
        for (int j = 0; j < 4; j++) wmma::fill_fragment(acc[i][j], 0.f);

    ldgA(0); stageB1(0); cp_commit(); stsA(0); ldgA(1);

    #pragma unroll 1
    for (int c = 0; c < 4; ++c) {
        cp_wait0();
        __syncthreads();
        if (c + 1 < 4) { stageB1(c + 1); cp_commit(); }
        const __half* ab = (const __half*)(smc + SE_A(c & 1));
        const __half* bb = (const __half*)(smc + SE_B1(c & 1));
        #pragma unroll
        for (int kk = 0; kk < 32; kk += 16) {
            AFrag a0, a1;
            wmma::load_matrix_sync(a0, ab + (wm * 32)      * LDA_E + kk, LDA_E);
            wmma::load_matrix_sync(a1, ab + (wm * 32 + 16) * LDA_E + kk, LDA_E);
            #pragma unroll
            for (int j = 0; j < 4; j++) {
                BFrag b;
                wmma::load_matrix_sync(b, bb + kk * LDB1 + wn * 64 + j * 16, LDB1);
                wmma::mma_sync(acc[0][j], a0, b, acc[0][j]);
                wmma::mma_sync(acc[1][j], a1, b, acc[1][j]);
            }
        }
        if (c + 1 < 4) { stsA(c + 1); if (c + 2 < 4) ldgA(c + 2); }
    }
    __syncthreads();          // GEMM1a done; A + B1 regions dead; meshH landed

    stageB2(0); cp_commit();  // into dead A/B1 space, overlaps gather+transition

    // ---------------- gather gridH[dst], sum into HH (in place) --------------
    {
        const uint4* gh = (const uint4*)(g_gridH + (size_t)didx * 256 + q * 64);
        uint4* hrow = (uint4*)(smc + SE_HH + (r * LDHH + q * 64) * 2);
        #pragma unroll
        for (int w = 0; w < 2; ++w) {
            uint4 gld[4];
            #pragma unroll
            for (int i = 0; i < 4; ++i) gld[i] = __ldg(gh + w * 4 + i);
            #pragma unroll
            for (int i = 0; i < 4; ++i)
                hrow[w * 4 + i] = hadd2u4(hrow[w * 4 + i], gld[i]);
        }
    }
    __syncthreads();

    // ---------------- transition: acc + b1 + MGH -> SiLU -> HH (in place) ----
    {
        float* scr = (float*)(smc + SE_SCR(warp));
        const float* sb1 = (const float*)(smc + SM_CONST_B1);
        const int rr = lane >> 1, ch = (lane & 1) * 8;
        #pragma unroll
        for (int i = 0; i < 2; i++)
            #pragma unroll
            for (int j = 0; j < 4; j++) {
                wmma::store_matrix_sync(scr, acc[i][j], LDSCR, wmma::mem_row_major);
                __syncwarp();
                const float* p = scr + rr * LDSCR + ch;
                float4 x0 = *(const float4*)(p);
                float4 x1 = *(const float4*)(p + 4);
                int cbase = wn * 64 + j * 16 + ch;
                int rowg = wm * 32 + i * 16 + rr;
                uint4 mg = *(uint4*)(smc + SE_HH + (rowg * LDHH + cbase) * 2);
                float2 m0 = __half22float2(*reinterpret_cast<__half2*>(&mg.x));
                float2 m1 = __half22float2(*reinterpret_cast<__half2*>(&mg.y));
                float2 m2 = __half22float2(*reinterpret_cast<__half2*>(&mg.z));
                float2 m3 = __half22float2(*reinterpret_cast<__half2*>(&mg.w));
                float4 bb0 = *(const float4*)(sb1 + cbase);
                float4 bb1 = *(const float4*)(sb1 + cbase + 4);
                x0.x += bb0.x + m0.x; x0.y += bb0.y + m0.y;
                x0.z += bb0.z + m1.x; x0.w += bb0.w + m1.y;
                x1.x += bb1.x + m2.x; x1.y += bb1.y + m2.y;
                x1.z += bb1.z + m3.x; x1.w += bb1.w + m3.y;
                *(uint4*)(smc + SE_HH + (rowg * LDHH + cbase) * 2) =
                    pack8h(silu4(x0), silu4(x1));
                __syncwarp();
            }
    }

    // ---------------- GEMM2: [64,256]x[256,128], 4 K64 chunks ----------------
    CFrag acc2[2][2];
    #pragma unroll
    for (int i = 0; i < 2; i++)
        #pragma unroll
        for (int j = 0; j < 2; j++) wmma::fill_fragment(acc2[i][j], 0.f);

    const __half* hh = (const __half*)(smc + SE_HH);
    #pragma unroll 1
    for (int c = 0; c < 4; ++c) {
        cp_wait0();
        __syncthreads();      // HH fully written (c=0); B2 buffer free
        if (c + 1 < 4) { stageB2(c + 1); cp_commit(); }
        const __half* bb = (const __half*)(smc + SE_B2(c & 1));
        #pragma unroll
        for (int kk = 0; kk < 64; kk += 16) {
            AFrag a0, a1;
            wmma::load_matrix_sync(a0, hh + (wm * 32)      * LDHH + c * 64 + kk, LDHH);
            wmma::load_matrix_sync(a1, hh + (wm * 32 + 16) * LDHH + c * 64 + kk, LDHH);
            #pragma unroll
            for (int j = 0; j < 2; j++) {
                BFrag b;
                wmma::load_matrix_sync(b, bb + kk * LDB2 + wn * 32 + j * 16, LDB2);
                wmma::mma_sync(acc2[0][j], a0, b, acc2[0][j]);
                wmma::mma_sync(acc2[1][j], a1, b, acc2[1][j]);
            }
        }
    }
    __syncthreads();          // all MMAs done; HH region reusable as Y
    float* yf = (float*)(smc + SE_Y);
    #pragma unroll
    for (int i = 0; i < 2; i++)
        #pragma unroll
        for (int j = 0; j < 2; j++)
            wmma::store_matrix_sync(yf + (wm * 32 + i * 16) * LDY + wn * 32 + j * 16,
                                    acc2[i][j], LDY, wmma::mem_row_major);
    __syncthreads();

    // ---------------- +b2, LN, vector-red scatter ----------------
    float4 bb2 = *(const float4*)(smc + SM_CONST_B2 + lane * 16);
    float4 gg  = *(const float4*)(smc + SM_CONST_G  + lane * 16);
    float4 bt  = *(const float4*)(smc + SM_CONST_BT + lane * 16);
    #pragma unroll 1
    for (int i = 0; i < 8; i++) {
        int row = warp * 8 + i;
        float4 v = *(const float4*)(yf + row * LDY + lane * 4);
        v.x += bb2.x; v.y += bb2.y; v.z += bb2.z; v.w += bb2.w;
        float sum = v.x + v.y + v.z + v.w;
        float sq  = v.x * v.x + v.y * v.y + v.z * v.z + v.w * v.w;
        #pragma unroll
        for (int o = 16; o > 0; o >>= 1) {
            sum += __shfl_xor_sync(0xFFFFFFFFu, sum, o);
            sq  += __shfl_xor_sync(0xFFFFFFFFu, sq,  o);
        }
        float mean = sum * (1.f / 128.f);
        float rstd = rsqrtf(sq * (1.f / 128.f) - mean * mean + 1e-5f);
        int dn = __ldg(&dst[e0 + row]);
        float4 o;
        o.x = (v.x - mean) * rstd * gg.x + bt.x;
        o.y = (v.y - mean) * rstd * gg.y + bt.y;
        o.z = (v.z - mean) * rstd * gg.z + bt.z;
        o.w = (v.w - mean) * rstd * gg.w + bt.w;
        red_add_v4(g_agg + (size_t)dn * 128 + lane * 4, o);
    }
}

// ------------------------------ node kernel (unchanged R8) -------------------
__global__ void __launch_bounds__(NTHR, 2)
node_kernel(const float* __restrict__ gridf,
            const float* __restrict__ b1, const float* __restrict__ b2,
            const float* __restrict__ gam, const float* __restrict__ bet,
            float* __restrict__ out)
{
    extern __shared__ char smc[];
    const uint32_t sb = smem_u32(smc);
    const int tid  = threadIdx.x;
    const int warp = tid >> 5, lane = tid & 31;
    const int wm = warp >> 2, wn = warp & 3;
    const int n0 = blockIdx.x * MT;

    if (tid < 64) ((float4*)(smc + SM_CONST_B1))[tid] = ((const float4*)b1)[tid];
    else if (tid < 96)  ((float4*)(smc + SM_CONST_B2))[tid - 64] = ((const float4*)b2)[tid - 64];
    else if (tid < 128) ((float4*)(smc + SM_CONST_G ))[tid - 96] = ((const float4*)gam)[tid - 96];
    else if (tid < 160) ((float4*)(smc + SM_CONST_BT))[tid - 128] = ((const float4*)bet)[tid - 128];

    const int r  = tid >> 2;
    const int cb = (tid & 3) * 16;
    const float* rowA = g_agg + (size_t)(n0 + r) * 128;
    const float* rowG = gridf + (size_t)(n0 + r) * 128;

    float4 v0, v1, v2, v3;
    auto ldgA = [&](int c) {
        const float* rp = (c < 2) ? rowA : rowG;
        const float4* gp = (const float4*)(rp + (c & 1) * 64 + cb);
        v0 = __ldg(gp); v1 = __ldg(gp + 1); v2 = __ldg(gp + 2); v3 = __ldg(gp + 3);
    };
    auto stsA = [&](int c) {
        char* d = smc + SM_A(c & 1) + (r * LDA + cb) * 2;
        *(uint4*)(d)      = pack8h(v0, v1);
        *(uint4*)(d + 16) = pack8h(v2, v3);
    };
    auto stageB1 = [&](int c) {
        uint32_t bb = sb + SM_B1(c & 1);
        const __half* gw = g_W1n + c * 64 * 256;
        #pragma unroll
        for (int i = 0; i < 8; ++i) {
            int id = tid + NTHR * i; int rw = id >> 5, c16 = id & 31;
            cpa16(bb + (uint32_t)(rw * LDB1 + c16 * 8) * 2, gw + rw * 256 + c16 * 8);
        }
    };
    auto stageB2 = [&](int c) {
        uint32_t bb = sb + SM_B2(c & 1);
        const __half* gw = g_W2n + c * 64 * 128;
        #pragma unroll
        for (int i = 0; i < 4; ++i) {
            int id = tid + NTHR * i; int rw = id >> 4, c16 = id & 15;
            cpa16(bb + (uint32_t)(rw * LDB2 + c16 * 8) * 2, gw + rw * 128 + c16 * 8);
        }
    };

    CFrag acc[2][4];
    #pragma unroll
    for (int i = 0; i < 2; i++)
        #pragma unroll
        for (int j = 0; j < 4; j++) wmma::fill_fragment(acc[i][j], 0.f);

    ldgA(0); stageB1(0); cp_commit(); stsA(0); ldgA(1);

    #pragma unroll 1
    for (int c = 0; c < 4; ++c) {
        cp_wait0();
        __syncthreads();
        if (c + 1 < 4) { stageB1(c + 1); cp_commit(); }
        const __half* ab = (const __half*)(smc + SM_A(c & 1));
        const __half* bb = (const __half*)(smc + SM_B1(c & 1));
        #pragma unroll
        for (int kk = 0; kk < 64; kk += 16) {
            AFrag a0, a1;
            wmma::load_matrix_sync(a0, ab + (wm * 32)      * LDA + kk, LDA);
            wmma::load_matrix_sync(a1, ab + (wm * 32 + 16) * LDA + kk, LDA);
            #pragma unroll
            for (int j = 0; j < 4; j++) {
                BFrag b;
                wmma::load_matrix_sync(b, bb + kk * LDB1 + wn * 64 + j * 16, LDB1);
                wmma::mma_sync(acc[0][j], a0, b, acc[0][j]);
                wmma::mma_sync(acc[1][j], a1, b, acc[1][j]);
            }
        }
        if (c + 1 < 4) { stsA(c + 1); if (c + 2 < 4) ldgA(c + 2); }
    }
    __syncthreads();

    stageB2(0); cp_commit();

    {
        float* scr = (float*)(smc + SM_SCR(warp));
        const float* sb1 = (const float*)(smc + SM_CONST_B1);
        const int rr = lane >> 1, ch = (lane & 1) * 8;
        #pragma unroll
        for (int i = 0; i < 2; i++)
            #pragma unroll
            for (int j = 0; j < 4; j++) {
                wmma::store_matrix_sync(scr, acc[i][j], LDSCR, wmma::mem_row_major);
                __syncwarp();
                const float* p = scr + rr * LDSCR + ch;
                float4 x0 = *(const float4*)(p);
                float4 x1 = *(const float4*)(p + 4);
                int cbase = wn * 64 + j * 16 + ch;
                float4 bb0 = *(const float4*)(sb1 + cbase);
                float4 bb1 = *(const float4*)(sb1 + cbase + 4);
                x0.x += bb0.x; x0.y += bb0.y; x0.z += bb0.z; x0.w += bb0.w;
                x1.x += bb1.x; x1.y += bb1.y; x1.z += bb1.z; x1.w += bb1.w;
                int rowg = wm * 32 + i * 16 + rr;
                *(uint4*)(smc + SM_HH + (rowg * LDHH + cbase) * 2) =
                    pack8h(silu4(x0), silu4(x1));
                __syncwarp();
            }
    }

    CFrag acc2[2][2];
    #pragma unroll
    for (int i = 0; i < 2; i++)
        #pragma unroll
        for (int j = 0; j < 2; j++) wmma::fill_fragment(acc2[i][j], 0.f);

    const __half* hh = (const __half*)(smc + SM_HH);
    #pragma unroll 1
    for (int c = 0; c < 4; ++c) {
        cp_wait0();
        __syncthreads();
        if (c + 1 < 4) { stageB2(c + 1); cp_commit(); }
        const __half* bb = (const __half*)(smc + SM_B2(c & 1));
        #pragma unroll
        for (int kk = 0; kk < 64; kk += 16) {
            AFrag a0, a1;
            wmma::load_matrix_sync(a0, hh + (wm * 32)      * LDHH + c * 64 + kk, LDHH);
            wmma::load_matrix_sync(a1, hh + (wm * 32 + 16) * LDHH + c * 64 + kk, LDHH);
            #pragma unroll
            for (int j = 0; j < 2; j++) {
                BFrag b;
                wmma::load_matrix_sync(b, bb + kk * LDB2 + wn * 32 + j * 16, LDB2);
                wmma::mma_sync(acc2[0][j], a0, b, acc2[0][j]);
                wmma::mma_sync(acc2[1][j], a1, b, acc2[1][j]);
            }
        }
    }
    __syncthreads();
    float* yf = (float*)(smc + SM_Y);
    #pragma unroll
    for (int i = 0; i < 2; i++)
        #pragma unroll
        for (int j = 0; j < 2; j++)
            wmma::store_matrix_sync(yf + (wm * 32 + i * 16) * LDY + wn * 32 + j * 16,
                                    acc2[i][j], LDY, wmma::mem_row_major);
    __syncthreads();

    float4 bb2 = *(const float4*)(smc + SM_CONST_B2 + lane * 16);
    float4 gg  = *(const float4*)(smc + SM_CONST_G  + lane * 16);
    float4 bt  = *(const float4*)(smc + SM_CONST_BT + lane * 16);
    #pragma unroll 1
    for (int i = 0; i < 8; i++) {
        int row = warp * 8 + i;
        float4 v = *(const float4*)(yf + row * LDY + lane * 4);
        v.x += bb2.x; v.y += bb2.y; v.z += bb2.z; v.w += bb2.w;
        float sum = v.x + v.y + v.z + v.w;
        float sq  = v.x * v.x + v.y * v.y + v.z * v.z + v.w * v.w;
        #pragma unroll
        for (int o = 16; o > 0; o >>= 1) {
            sum += __shfl_xor_sync(0xFFFFFFFFu, sum, o);
            sq  += __shfl_xor_sync(0xFFFFFFFFu, sq,  o);
        }
        float mean = sum * (1.f / 128.f);
        float rstd = rsqrtf(sq * (1.f / 128.f) - mean * mean + 1e-5f);
        size_t base = (size_t)(n0 + row) * 128;
        float4 gv = __ldg((const float4*)(gridf + base) + lane);
        float4 o;
        o.x = (v.x - mean) * rstd * gg.x + bt.x + gv.x;
        o.y = (v.y - mean) * rstd * gg.y + bt.y + gv.y;
        o.z = (v.z - mean) * rstd * gg.z + bt.z + gv.z;
        o.w = (v.w - mean) * rstd * gg.w + bt.w + gv.w;
        *((float4*)(out + base) + lane) = o;
    }
}

// ------------------------------ launch --------------------------------------
extern "C" void kernel_launch(void* const* d_in, const int* in_sizes, int n_in,
                              void* d_out, int out_size)
{
    const float* efeat = (const float*)d_in[0];
    const float* gridf = (const float*)d_in[1];
    const float* mesh  = (const float*)d_in[2];
    const int*   src   = (const int*)d_in[3];
    const int*   dst   = (const int*)d_in[4];
    const float* eW1   = (const float*)d_in[5];
    const float* eb1   = (const float*)d_in[6];
    const float* eW2   = (const float*)d_in[7];
    const float* eb2   = (const float*)d_in[8];
    const float* eg    = (const float*)d_in[9];
    const float* ebeta = (const float*)d_in[10];
    const float* nW1   = (const float*)d_in[11];
    const float* nb1   = (const float*)d_in[12];
    const float* nW2   = (const float*)d_in[13];
    const float* nb2   = (const float*)d_in[14];
    const float* ng    = (const float*)d_in[15];
    const float* nbeta = (const float*)d_in[16];
    float* out = (float*)d_out;

    static __half* meshH_ptr = nullptr;
    static __half* gridH_ptr = nullptr;
    if (!meshH_ptr) {
        cudaGetSymbolAddress((void**)&meshH_ptr, g_meshH);
        cudaGetSymbolAddress((void**)&gridH_ptr, g_gridH);
    }

    cudaFuncSetAttribute(edge_kernel,  cudaFuncAttributeMaxDynamicSharedMemorySize, SE_SMEM);
    cudaFuncSetAttribute(node_kernel,  cudaFuncAttributeMaxDynamicSharedMemorySize, SMEM_BYTES);
    cudaFuncSetAttribute(prepH_kernel, cudaFuncAttributeMaxDynamicSharedMemorySize, PH_SMEM);

    zero_agg_kernel<<<8192, 1024>>>();
    prep_kernel<<<896, 256>>>(eW1, eW2, nW1, nW2);
    prepH_kernel<<<(N_MESH + MT - 1) / MT, NTHR, PH_SMEM>>>(mesh, N_MESH, 0, meshH_ptr);
    prepH_kernel<<<N_GRID / MT, NTHR, PH_SMEM>>>(gridf, N_GRID, 1, gridH_ptr);
    edge_kernel<<<N_EDGE / MT, NTHR, SE_SMEM>>>(efeat, src, dst, eb1, eb2, eg, ebeta);
    node_kernel<<<N_GRID / MT, NTHR, SMEM_BYTES>>>(gridf, nb1, nb2, ng, nbeta, out);
}